// round 2
// baseline (speedup 1.0000x reference)
#include <cuda_runtime.h>
#include <cuda_fp16.h>

// Problem: M is [512, 65536] fp32. Sinkhorn loop, trip count in {1, 51, 100}.
#define NR    512
#define NC    65536
#define GRID  128              // <= SM count (148/152): wave-1 co-residency GUARANTEED
#define TPB   512
#define COLS_PER_BLK (NC / GRID)   // 512
#define ROWS_PER_BLK (NR / GRID)   // 4

// Persistent scratch (allocation rule: __device__ globals only)
__device__ __half   g_K[(size_t)NR * NC];     // 64 MB fp16 kernel matrix
__device__ float    g_v[2][NC];               // double-buffered v (by cpt parity)
__device__ __half2  g_vh[NC / 2];             // fp16 v for the row-reduce pass
__device__ float    g_u[NR];
__device__ float    g_errPart[2][GRID];
__device__ int      g_done_f;
__device__ int      g_final_f;
__device__ unsigned g_bar = 0;
__device__ volatile unsigned g_gen = 0;

// Software grid barrier. GRID <= #SMs guarantees all blocks co-resident, so
// this cannot deadlock; the spin cap (~20ms) is a belt-and-suspenders escape
// hatch that turns any residual bug into a wrong answer instead of a timeout.
__device__ __forceinline__ void gsync(unsigned &phase) {
    __syncthreads();
    if (threadIdx.x == 0) {
        ++phase;
        __threadfence();
        if (atomicAdd(&g_bar, 1u) == GRID - 1u) {
            g_bar = 0u;
            __threadfence();
            g_gen = phase;
        } else {
            unsigned spins = 0;
            while (g_gen < phase) {
                __nanosleep(64);
                if (++spins > (1u << 18)) break;   // escape hatch, never expected
            }
        }
    }
    __syncthreads();
}

__device__ __forceinline__ float blockReduce512(float v, float* sh) {
    const int t = threadIdx.x;
    sh[t] = v; __syncthreads();
    if (t < 256) sh[t] += sh[t + 256];
    __syncthreads();
    if (t < 128) sh[t] += sh[t + 128];
    __syncthreads();
    if (t < 64)  sh[t] += sh[t + 64];
    __syncthreads();
    if (t < 32) {
        float x = sh[t] + sh[t + 32];
        #pragma unroll
        for (int o = 16; o; o >>= 1) x += __shfl_down_sync(0xffffffffu, x, o);
        if (t == 0) sh[0] = x;
    }
    __syncthreads();
    float r = sh[0];
    __syncthreads();
    return r;
}

__global__ void __launch_bounds__(TPB, 1)
sinkhorn_all(const float* __restrict__ M, float* __restrict__ out) {
    __shared__ float sh[TPB];
    __shared__ float sh2[TPB];
    __shared__ float u_s[NR];
    unsigned phase = 0;
    const int tid = threadIdx.x;
    const int bid = blockIdx.x;

    // ---- init (block 0; TPB == NR == 512) ----
    if (bid == 0) {
        if (tid == 0) { out[0] = 0.0f; g_done_f = 0; g_final_f = 0; }
        g_u[tid] = 1.0f / NR;
    }

    // ---- precompute K = exp(-20*M) in fp16 (grid-stride, vectorized) ----
    {
        const float4* m4 = (const float4*)M;
        uint4* k8 = (uint4*)g_K;
        const unsigned total8 = ((unsigned)NR * (unsigned)NC) / 8u;   // 4M
        for (unsigned idx = (unsigned)bid * TPB + tid; idx < total8; idx += (unsigned)GRID * TPB) {
            float4 a = m4[2u * idx];
            float4 b = m4[2u * idx + 1u];
            union { __half2 h[4]; uint4 u; } pk;
            pk.h[0] = __floats2half2_rn(__expf(-20.0f * a.x), __expf(-20.0f * a.y));
            pk.h[1] = __floats2half2_rn(__expf(-20.0f * a.z), __expf(-20.0f * a.w));
            pk.h[2] = __floats2half2_rn(__expf(-20.0f * b.x), __expf(-20.0f * b.y));
            pk.h[3] = __floats2half2_rn(__expf(-20.0f * b.z), __expf(-20.0f * b.w));
            k8[idx] = pk.u;
        }
    }
    gsync(phase);

    // ---- Sinkhorn loop (matches reference trip semantics: exits at cpt 1/51/100) ----
    for (int cpt = 1; cpt <= 100; ++cpt) {
        const bool errIter = (cpt == 2) || (cpt == 52);

        // Phase A: t_j = sum_i K_ij*u_i ; v_j = b/(t_j+eps).
        // Block owns 512 cols. Thread map: p = col-pair (256), rh = row half (2).
        u_s[tid] = __ldcg(&g_u[tid]);
        __syncthreads();

        const int p  = tid & 255;
        const int rh = tid >> 8;
        const int j0 = bid * COLS_PER_BLK + 2 * p;
        float s0 = 0.0f, s1 = 0.0f;
        if (!errIter) {
            const __half2* kp = (const __half2*)g_K + (size_t)(rh * 256) * (NC / 2) + (j0 >> 1);
            const float*   us = u_s + rh * 256;
            #pragma unroll 16
            for (int r = 0; r < 256; ++r) {
                float2 kf = __half22float2(kp[(size_t)r * (NC / 2)]);
                float  u  = us[r];
                s0 = fmaf(kf.x, u, s0);
                s1 = fmaf(kf.y, u, s1);
            }
        } else {
            // Branch-critical iteration: fp32 K recomputed from M so the
            // err-vs-0.005 decision tracks the fp32 reference.
            const float2* mp = (const float2*)M + (size_t)(rh * 256) * (NC / 2) + (j0 >> 1);
            const float*  us = u_s + rh * 256;
            #pragma unroll 8
            for (int r = 0; r < 256; ++r) {
                float2 mf = mp[(size_t)r * (NC / 2)];
                float  u  = us[r];
                s0 = fmaf(__expf(-20.0f * mf.x), u, s0);
                s1 = fmaf(__expf(-20.0f * mf.y), u, s1);
            }
        }
        sh[tid] = s0; sh2[tid] = s1;
        __syncthreads();
        float t0 = 0.0f, t1 = 0.0f;
        if (tid < 256) { t0 = sh[tid] + sh[tid + 256]; t1 = sh2[tid] + sh2[tid + 256]; }
        __syncthreads();

        if (errIter) {
            // err_{cpt-1} = sum_j |v_{cpt-1,j}*(K^T u_{cpt-1})_j - b_j|
            // (cpt-1) is 1 or 51 -> both odd -> prev v lives in g_v[1].
            float e = 0.0f;
            if (tid < 256) {
                const int jj = bid * COLS_PER_BLK + 2 * tid;
                float v0p = g_v[1][jj], v1p = g_v[1][jj + 1];
                e = fabsf(v0p * t0 - (1.0f / NC)) + fabsf(v1p * t1 - (1.0f / NC));
            }
            float etot = blockReduce512(e, sh);
            if (tid == 0) g_errPart[(cpt == 2) ? 0 : 1][bid] = etot;
        }
        if (tid < 256) {
            const int jj = bid * COLS_PER_BLK + 2 * tid;
            float v0 = (1.0f / NC) / (t0 + 1e-16f);
            float v1 = (1.0f / NC) / (t1 + 1e-16f);
            g_v[cpt & 1][jj]     = v0;
            g_v[cpt & 1][jj + 1] = v1;
            g_vh[jj >> 1] = __floats2half2_rn(v0, v1);
        }
        gsync(phase);

        if (errIter) {
            if (bid == 0) {
                const int slot = (cpt == 2) ? 0 : 1;
                float e = (tid < GRID) ? __ldcg(&g_errPart[slot][tid]) : 0.0f;
                float etot = blockReduce512(e, sh);
                if (tid == 0 && etot <= 0.005f) { g_done_f = 1; g_final_f = 1; }
            }
            gsync(phase);
            if (__ldcg(&g_done_f)) break;   // uniform across all blocks
        }

        // Phase C: s_i = sum_j K_ij*v_j ; u_i = a/(s_i+eps). 4 rows/block.
        {
            const int row = bid * ROWS_PER_BLK + (tid >> 7);
            const int l   = tid & 127;
            const uint4* kp = (const uint4*)(g_K + (size_t)row * NC);
            const uint4* vp = (const uint4*)g_vh;
            float s = 0.0f;
            #pragma unroll 4
            for (int c = l; c < NC / 8; c += 128) {
                uint4 kk = kp[c];
                uint4 vv = __ldcg(vp + c);   // cross-block data; L2-resident (128 KB)
                const __half2* kh  = (const __half2*)&kk;
                const __half2* vh2 = (const __half2*)&vv;
                #pragma unroll
                for (int q = 0; q < 4; ++q) {
                    float2 kf = __half22float2(kh[q]);
                    float2 vf = __half22float2(vh2[q]);
                    s = fmaf(kf.x, vf.x, s);
                    s = fmaf(kf.y, vf.y, s);
                }
            }
            sh[tid] = s; __syncthreads();
            if (l < 64) sh[tid] += sh[tid + 64];
            __syncthreads();
            if (l < 32) {
                float x = sh[tid] + sh[tid + 32];
                #pragma unroll
                for (int o = 16; o; o >>= 1) x += __shfl_down_sync(0xffffffffu, x, o);
                if (l == 0) g_u[row] = (1.0f / NR) / (x + 1e-16f);
            }
            __syncthreads();
        }
        gsync(phase);
    }

    // ---- loss = 100 * sum_ij u_i * exp(-20 M_ij) * v_j * M_ij  (4 rows/block) ----
    {
        const int   f   = __ldcg(&g_final_f);
        const int   row = bid * ROWS_PER_BLK + (tid >> 7);
        const int   l   = tid & 127;
        const float ui  = __ldcg(&g_u[row]);
        const float4* mp = (const float4*)(M + (size_t)row * NC);
        const float4* vp = (const float4*)(f ? g_v[1] : g_v[0]);
        float s = 0.0f;
        #pragma unroll 4
        for (int c = l; c < NC / 4; c += 128) {
            float4 mm = mp[c];
            float4 vv = __ldcg(vp + c);
            s = fmaf(__expf(-20.0f * mm.x) * vv.x, mm.x, s);
            s = fmaf(__expf(-20.0f * mm.y) * vv.y, mm.y, s);
            s = fmaf(__expf(-20.0f * mm.z) * vv.z, mm.z, s);
            s = fmaf(__expf(-20.0f * mm.w) * vv.w, mm.w, s);
        }
        sh[tid] = s; __syncthreads();
        if (l < 64) sh[tid] += sh[tid + 64];
        __syncthreads();
        if (l < 32) {
            float x = sh[tid] + sh[tid + 32];
            #pragma unroll
            for (int o = 16; o; o >>= 1) x += __shfl_down_sync(0xffffffffu, x, o);
            if (l == 0) atomicAdd(out, 100.0f * ui * x);
        }
    }
    gsync(phase);
    if (bid == 0 && tid == 0) g_gen = 0;   // clean barrier state for next graph replay
}

extern "C" void kernel_launch(void* const* d_in, const int* in_sizes, int n_in,
                              void* d_out, int out_size) {
    const float* M = (const float*)d_in[0];
    float* out = (float*)d_out;
    sinkhorn_all<<<GRID, TPB>>>(M, out);
}

// round 3
// speedup vs baseline: 1.1581x; 1.1581x over previous
#include <cuda_runtime.h>
#include <cuda_fp16.h>

// M is [512, 65536] fp32. Sinkhorn: trip count in {1, 51, 100}; this input exits at 1.
#define NR    512
#define NC    65536
#define GRID  128              // <= SM count: wave-1 co-residency guaranteed
#define TPB   512
#define CPB   (NC / GRID)      // 512 columns per block (block owns full column stripe)

// Persistent scratch (__device__ globals per allocation rule)
__device__ __half   g_K[(size_t)NR * NC];     // 64 MB fp16 kernel matrix
__device__ float    g_u[NR];
__device__ float    g_sPart[GRID * NR];       // [bid][row] row-sum partials
__device__ float    g_errPart[GRID];
__device__ float    g_lossPart[GRID];
__device__ int      g_done;
__device__ unsigned g_bar = 0;
__device__ volatile unsigned g_gen = 0;       // monotone across graph replays

// Grid barrier: GRID <= #SMs -> cannot deadlock. Spin cap = escape hatch only.
__device__ __forceinline__ void gsync(unsigned &phase) {
    __syncthreads();
    if (threadIdx.x == 0) {
        ++phase;
        __threadfence();
        if (atomicAdd(&g_bar, 1u) == GRID - 1u) {
            g_bar = 0u;
            __threadfence();
            g_gen = phase;
        } else {
            unsigned spins = 0;
            while (g_gen < phase) {
                __nanosleep(64);
                if (++spins > (1u << 18)) break;
            }
        }
    }
    __syncthreads();
}

__device__ __forceinline__ float blockReduce512(float x, float* sh) {
    const int t = threadIdx.x;
    sh[t] = x; __syncthreads();
    if (t < 256) sh[t] += sh[t + 256];
    __syncthreads();
    if (t < 128) sh[t] += sh[t + 128];
    __syncthreads();
    if (t < 64)  sh[t] += sh[t + 64];
    __syncthreads();
    if (t < 32) {
        float v = sh[t] + sh[t + 32];
        #pragma unroll
        for (int o = 16; o; o >>= 1) v += __shfl_down_sync(0xffffffffu, v, o);
        if (t == 0) sh[0] = v;
    }
    __syncthreads();
    float r = sh[0];
    __syncthreads();
    return r;
}

__global__ void __launch_bounds__(TPB, 1)
sinkhorn_all(const float* __restrict__ M, float* __restrict__ out) {
    __shared__ float sh[TPB];
    __shared__ float sh_u[NR];
    __shared__ float sh_v[CPB];
    const int tid = threadIdx.x;
    const int bid = blockIdx.x;
    unsigned phase = g_gen;                   // continue generation across replays

    const int    j  = bid * CPB + tid;        // owned column
    const float* Mj = M + j;

    float v;                                  // v_j for the current iteration (register)

    // ===== c = 1, phase A fused with exp precompute: t_j = (1/NR) * sum_i K_ij =====
    {
        float t = 0.0f;
        #pragma unroll 16
        for (int r = 0; r < NR; ++r) {
            float m = Mj[(size_t)r * NC];
            float k = __expf(-20.0f * m);
            g_K[(size_t)r * NC + j] = __float2half(k);
            t += k;
        }
        t *= (1.0f / NR);
        v = (1.0f / NC) / (t + 1e-16f);
    }
    __syncthreads();                          // K stripe visible within block

    // ---- phase C (inlined below via macro-less lambda pattern) ----
    // row partials over own stripe -> gsync -> u reduce -> gsync
    #define PHASE_C()                                                              \
    {                                                                              \
        sh_v[tid] = v; __syncthreads();                                            \
        float s = 0.0f;                                                            \
        const uint4* kp = (const uint4*)(g_K + (size_t)tid * NC + bid * CPB);      \
        _Pragma("unroll 8")                                                        \
        for (int c4 = 0; c4 < CPB / 8; ++c4) {                                     \
            uint4 kk = kp[c4];                                                     \
            const __half2* kh = (const __half2*)&kk;                               \
            const float* vv = &sh_v[c4 * 8];                                       \
            _Pragma("unroll")                                                      \
            for (int q = 0; q < 4; ++q) {                                          \
                float2 kf = __half22float2(kh[q]);                                 \
                s = fmaf(kf.x, vv[2 * q],     s);                                  \
                s = fmaf(kf.y, vv[2 * q + 1], s);                                  \
            }                                                                      \
        }                                                                          \
        g_sPart[bid * NR + tid] = s;                                               \
        gsync(phase);                                                              \
        {                                                                          \
            const int p = tid & 127, rr = tid >> 7;                                \
            const int row = bid * 4 + rr;                                          \
            float val = __ldcg(&g_sPart[p * NR + row]);                            \
            sh[tid] = val; __syncthreads();                                        \
            if (p < 64) sh[tid] += sh[tid + 64];                                   \
            __syncthreads();                                                       \
            if (p < 32) {                                                          \
                float x = sh[tid] + sh[tid + 32];                                  \
                _Pragma("unroll")                                                  \
                for (int o = 16; o; o >>= 1)                                       \
                    x += __shfl_down_sync(0xffffffffu, x, o);                      \
                if (p == 0) g_u[row] = (1.0f / NR) / (x + 1e-16f);                 \
            }                                                                      \
            __syncthreads();                                                       \
        }                                                                          \
        gsync(phase);                                                              \
    }

    // ---- fused err + loss pass (fp32 exp from M; used at c=1 and c=51) ----
    // Computes t' = K^T u (fp32), err = sum|v*t' - b|, loss = sum u*K*M*v.
    // If done: block 0 writes out. Else: v <- b/(t'+eps) becomes v_{c+1}.
    #define FUSED_ERR(done_var)                                                    \
    {                                                                              \
        sh_u[tid] = __ldcg(&g_u[tid]); __syncthreads();                            \
        float tp = 0.0f, la = 0.0f;                                                \
        _Pragma("unroll 16")                                                       \
        for (int r = 0; r < NR; ++r) {                                             \
            float m = Mj[(size_t)r * NC];                                          \
            float k = __expf(-20.0f * m);                                          \
            float u = sh_u[r];                                                     \
            tp = fmaf(k, u, tp);                                                   \
            la = fmaf(k * m, u, la);                                               \
        }                                                                          \
        float errj  = fabsf(v * tp - (1.0f / NC));                                 \
        float lossj = v * la;                                                      \
        float eb = blockReduce512(errj, sh);                                       \
        float lb = blockReduce512(lossj, sh);                                      \
        if (tid == 0) { g_errPart[bid] = eb; g_lossPart[bid] = lb; }               \
        float vn = (1.0f / NC) / (tp + 1e-16f);                                    \
        gsync(phase);                                                              \
        if (bid == 0) {                                                            \
            float ep = (tid < GRID) ? __ldcg(&g_errPart[tid]) : 0.0f;              \
            float et = blockReduce512(ep, sh);                                     \
            int dn = (et <= 0.005f);                                               \
            if (dn) {                                                              \
                float lp = (tid < GRID) ? __ldcg(&g_lossPart[tid]) : 0.0f;         \
                float lt = blockReduce512(lp, sh);                                 \
                if (tid == 0) out[0] = 100.0f * lt;                                \
            }                                                                      \
            if (tid == 0) g_done = dn;                                             \
        }                                                                          \
        gsync(phase);                                                              \
        v = vn;                                                                    \
        done_var = __ldcg(&g_done);                                                \
    }

    // ===== iteration 1: phase C -> u_1, then err check (fused with loss) =====
    PHASE_C();
    int done;
    FUSED_ERR(done);
    if (done) return;                         // trip-1 fast path: everything written

    // ===== generic iterations c = 2..100 =====
    for (int c = 2; c <= 100; ++c) {
        if (c > 2 && c != 52) {
            // phase A: t_j = sum_i K_ij * u_i (fp16 K), v_j = b/(t+eps)
            sh_u[tid] = __ldcg(&g_u[tid]); __syncthreads();
            float t = 0.0f;
            const __half* kc = g_K + j;
            #pragma unroll 16
            for (int r = 0; r < NR; ++r)
                t = fmaf(__half2float(kc[(size_t)r * NC]), sh_u[r], t);
            v = (1.0f / NC) / (t + 1e-16f);
        } // c==2 / c==52: v already produced by FUSED_ERR (fp32, matches reference)

        PHASE_C();                            // u_c

        if (c == 51) {
            FUSED_ERR(done);
            if (done) return;
        }
    }

    // ===== cap exit (cpt=100): standalone loss with u_100, v_100 =====
    {
        sh_u[tid] = __ldcg(&g_u[tid]); __syncthreads();
        float la = 0.0f;
        #pragma unroll 8
        for (int r = 0; r < NR; ++r) {
            float m = Mj[(size_t)r * NC];
            float k = __expf(-20.0f * m);
            la = fmaf(k * m, sh_u[r], la);
        }
        float lb = blockReduce512(v * la, sh);
        if (tid == 0) g_lossPart[bid] = lb;
        gsync(phase);
        if (bid == 0) {
            float lp = (tid < GRID) ? __ldcg(&g_lossPart[tid]) : 0.0f;
            float lt = blockReduce512(lp, sh);
            if (tid == 0) out[0] = 100.0f * lt;
        }
        gsync(phase);
    }
}

extern "C" void kernel_launch(void* const* d_in, const int* in_sizes, int n_in,
                              void* d_out, int out_size) {
    const float* M = (const float*)d_in[0];
    float* out = (float*)d_out;
    sinkhorn_all<<<GRID, TPB>>>(M, out);
}